// round 14
// baseline (speedup 1.0000x reference)
#include <cuda_runtime.h>
#include <cstdint>

#define BS 2
#define NF 16
#define C  32
#define H  128
#define W  128
#define HW (H*W)
#define NM 8
#define NK 3
#define MID (NF/2)

#define PCHUNK 128           // pixels per pool block
#define PNCH (HW/PCHUNK)     // 128 chunks
#define CG 4                 // channel groups (8 channels = 8 warps)
#define NBLK (PNCH*CG*BS)    // 1024 pool blocks

#define MPAIR 64             // pixel pairs per masks block

typedef unsigned long long ull;

// partials: row r=((b*C+c)*NM+m), PNCH floats per row (256 KB)
__device__ float        g_part[BS*C*NM*PNCH];
__device__ unsigned int g_ctr;   // zero-init; last pool block resets it

__device__ __forceinline__ ull pack2(float a, float b) {
    ull r; asm("mov.b64 %0,{%1,%2};" : "=l"(r) : "f"(a), "f"(b)); return r;
}

// ---------------------------------------------------------------------------
// Masks (K13 verbatim): grid (HW/2/MPAIR, BS) = 256 blocks, 256 threads.
// ---------------------------------------------------------------------------
__global__ void __launch_bounds__(256)
masks_kernel(const float* __restrict__ dec,
             const float* __restrict__ seg_w,
             const float* __restrict__ seg_b,
             float* __restrict__ masks_out)
{
    __shared__ float2 part[4][NM][MPAIR];   // 16 KB
    __shared__ float  sw[NM*C];             // 1 KB

    const int tid = threadIdx.x;
    if (tid < NM*C) sw[tid] = seg_w[tid];
    __syncthreads();

    const int b     = blockIdx.y;
    const int pair0 = blockIdx.x * MPAIR;
    const int pr    = tid & (MPAIR-1);
    const int qc    = tid >> 6;             // 0..3

    const float* src = dec + ((size_t)(b*NF + MID)*C + qc*8)*HW
                           + 2*(size_t)(pair0 + pr);
    float2 v[8];
#pragma unroll
    for (int i = 0; i < 8; i++)
        v[i] = *reinterpret_cast<const float2*>(src + (size_t)i*HW);

    float2 pm[NM];
#pragma unroll
    for (int m = 0; m < NM; m++) pm[m] = make_float2(0.f, 0.f);
#pragma unroll
    for (int i = 0; i < 8; i++)
#pragma unroll
        for (int m = 0; m < NM; m++) {
            float w = sw[m*C + qc*8 + i];
            pm[m].x += v[i].x * w;
            pm[m].y += v[i].y * w;
        }
#pragma unroll
    for (int m = 0; m < NM; m++) part[qc][m][pr] = pm[m];
    __syncthreads();

#pragma unroll
    for (int r = 0; r < 2; r++) {
        int k  = tid + r*256;
        int m  = k >> 6;
        int pp = k & (MPAIR-1);
        float2 a0 = part[0][m][pp], a1 = part[1][m][pp];
        float2 a2 = part[2][m][pp], a3 = part[3][m][pp];
        float bsc = seg_b[m];
        float2 o = make_float2(a0.x+a1.x+a2.x+a3.x + bsc,
                               a0.y+a1.y+a2.y+a3.y + bsc);
        *reinterpret_cast<float2*>(
            masks_out + ((size_t)b*NM + m)*HW + 2*(size_t)(pair0 + pp)) = o;
    }
}

// ---------------------------------------------------------------------------
// Pool + FENCE-FREE epilogue. Mainloop = K6 verbatim. No __threadfence
// (GPU-scope fence emits CCTL.IVALL -> flushes L1 in EVERY block; that was
// the K10-K12 regression). Counter uses atom.acq_rel; last block reads the
// partials via ld.global.cg (L2-direct) + one acq_rel fence in that block.
// ---------------------------------------------------------------------------
__global__ void __launch_bounds__(256, 2)
pool_kernel(const float* __restrict__ dec,
            const float* __restrict__ masks,
            const float* __restrict__ lw,
            const float* __restrict__ lb,
            float* __restrict__ logits_out)
{
    const int tid  = threadIdx.x;
    const int wid  = tid >> 5;
    const int lane = tid & 31;

    const int ch = blockIdx.x;
    const int cg = blockIdx.y;
    const int b  = blockIdx.z;
    const int c  = cg*8 + wid;

    ull mkA[NM], mkB[NM];
#pragma unroll
    for (int m = 0; m < NM; m++) {
        float4 mv = reinterpret_cast<const float4*>(
            masks + ((size_t)b*NM + m)*HW + (size_t)ch*PCHUNK)[lane];
        mkA[m] = pack2(mv.x, mv.y);
        mkB[m] = pack2(mv.z, mv.w);
    }

    ull acc[NM];
#pragma unroll
    for (int m = 0; m < NM; m++) acc[m] = 0ULL;

    const float* base = dec + ((size_t)b*NF*C + c)*HW + (size_t)ch*PCHUNK;

#pragma unroll 4
    for (int f = 0; f < NF; f++) {
        float4 v = reinterpret_cast<const float4*>(base + (size_t)f*C*HW)[lane];
        ull v01 = pack2(v.x, v.y);
        ull v23 = pack2(v.z, v.w);
#pragma unroll
        for (int m = 0; m < NM; m++) {
            asm("fma.rn.f32x2 %0, %1, %2, %0;" : "+l"(acc[m]) : "l"(v01), "l"(mkA[m]));
            asm("fma.rn.f32x2 %0, %1, %2, %0;" : "+l"(acc[m]) : "l"(v23), "l"(mkB[m]));
        }
    }

#pragma unroll
    for (int m = 0; m < NM; m++) {
        float2 a = *reinterpret_cast<float2*>(&acc[m]);
        float s = a.x + a.y;
#pragma unroll
        for (int off = 16; off; off >>= 1)
            s += __shfl_xor_sync(0xffffffffu, s, off);
        if (lane == 0)
            g_part[(((size_t)b*C + c)*NM + m)*PNCH + ch] = s;
    }

    // ---- epilogue gate: release-atomic counter, NO gpu fence here ----
    __shared__ bool is_last;
    __syncthreads();
    if (tid == 0) {
        unsigned old;
        asm volatile("atom.acq_rel.gpu.global.add.u32 %0, [%1], 1;"
                     : "=r"(old) : "l"(&g_ctr) : "memory");
        is_last = (old == NBLK - 1);
    }
    __syncthreads();
    if (!is_last) return;

    // one cheap acquire fence in this single block only
    asm volatile("fence.acq_rel.gpu;" ::: "memory");

    __shared__ float pooled[BS*NM*C];     // 2 KB

    // 512 rows / 256 threads = 2 rows each; ld.cg (L2-direct) float4 reads
#pragma unroll 1
    for (int r = 0; r < 2; r++) {
        int row = tid*2 + r;
        const float4* src = reinterpret_cast<const float4*>(
            g_part + (size_t)row*PNCH);
        float s = 0.f;
#pragma unroll 2
        for (int q = 0; q < PNCH/4; q++) {
            float4 a = __ldcg(src + q);
            s += (a.x + a.y) + (a.z + a.w);
        }
        int m  = row & (NM-1);
        int c2 = (row / NM) & (C-1);
        int b2 = row / (NM*C);
        pooled[((size_t)b2*NM + m)*C + c2] = s * (1.0f / NF);
    }
    __syncthreads();

    if (tid < BS*NM*NK) {
        int k  = tid % NK;
        int bm = tid / NK;
        const float* p = pooled + (size_t)bm*C;
        float acc2 = lb[k];
#pragma unroll 1
        for (int c2 = 0; c2 < C; c2++) acc2 += p[c2] * lw[k*C + c2];
        logits_out[tid] = acc2;
    }
    if (tid == 0) g_ctr = 0;              // reset for next graph replay
}

// ---------------------------------------------------------------------------
extern "C" void kernel_launch(void* const* d_in, const int* in_sizes, int n_in,
                              void* d_out, int out_size)
{
    const float* dec   = (const float*)d_in[0];
    const float* seg_w = (const float*)d_in[1];
    const float* seg_b = (const float*)d_in[2];
    const float* lw    = (const float*)d_in[3];
    const float* lb    = (const float*)d_in[4];

    float* out    = (float*)d_out;
    float* logits = out;                 // 48 floats
    float* masks  = out + BS*NM*NK;      // 262144 floats

    masks_kernel<<<dim3(HW/2/MPAIR, BS), 256>>>(dec, seg_w, seg_b, masks);
    pool_kernel <<<dim3(PNCH, CG, BS), 256>>>(dec, masks, lw, lb, logits);
}

// round 15
// speedup vs baseline: 1.2245x; 1.2245x over previous
#include <cuda_runtime.h>
#include <cstdint>

#define BS 2
#define NF 16
#define C  32
#define H  128
#define W  128
#define HW (H*W)
#define NM 8
#define NK 3
#define MID (NF/2)

#define PCHUNK 64            // pixels per pool block
#define PNCH (HW/PCHUNK)     // 256 chunks
#define PFG 8                // frames per pool block
#define PFS (NF/PFG)         // 2 frame splits
#define CG 4                 // channel groups of 8

#define MPAIR 64             // pixel pairs per masks block

typedef unsigned long long ull;

// partials: row r=((b*C+c)*NM+m), PFS*PNCH = 512 floats per row (1 MB)
__device__ float g_part[BS*C*NM*PFS*PNCH];
__device__ float g_pooled[BS*NM*C];
__device__ int   g_ctr;          // zero-init; self-resets each launch

// ---------------------------------------------------------------------------
// Masks (R10/K13 shape): grid (HW/2/MPAIR, BS) = 256 blocks, 256 threads.
// thread = (pair, qc); 8 float2 loads (MLP 8), smem combine, float2 stores.
// ---------------------------------------------------------------------------
__global__ void __launch_bounds__(256)
masks_kernel(const float* __restrict__ dec,
             const float* __restrict__ seg_w,
             const float* __restrict__ seg_b,
             float* __restrict__ masks_out)
{
    __shared__ float2 part[4][NM][MPAIR];   // 16 KB
    __shared__ float  sw[NM*C];             // 1 KB

    const int tid = threadIdx.x;
    if (tid < NM*C) sw[tid] = seg_w[tid];
    __syncthreads();

    const int b     = blockIdx.y;
    const int pair0 = blockIdx.x * MPAIR;
    const int pr    = tid & (MPAIR-1);
    const int qc    = tid >> 6;             // 0..3

    const float* src = dec + ((size_t)(b*NF + MID)*C + qc*8)*HW
                           + 2*(size_t)(pair0 + pr);
    float2 v[8];
#pragma unroll
    for (int i = 0; i < 8; i++)
        v[i] = *reinterpret_cast<const float2*>(src + (size_t)i*HW);

    float2 pm[NM];
#pragma unroll
    for (int m = 0; m < NM; m++) pm[m] = make_float2(0.f, 0.f);
#pragma unroll
    for (int i = 0; i < 8; i++)
#pragma unroll
        for (int m = 0; m < NM; m++) {
            float w = sw[m*C + qc*8 + i];
            pm[m].x += v[i].x * w;
            pm[m].y += v[i].y * w;
        }
#pragma unroll
    for (int m = 0; m < NM; m++) part[qc][m][pr] = pm[m];
    __syncthreads();

#pragma unroll
    for (int r = 0; r < 2; r++) {
        int k  = tid + r*256;
        int m  = k >> 6;
        int pp = k & (MPAIR-1);
        float2 a0 = part[0][m][pp], a1 = part[1][m][pp];
        float2 a2 = part[2][m][pp], a3 = part[3][m][pp];
        float bsc = seg_b[m];
        float2 o = make_float2(a0.x+a1.x+a2.x+a3.x + bsc,
                               a0.y+a1.y+a2.y+a3.y + bsc);
        *reinterpret_cast<float2*>(
            masks_out + ((size_t)b*NM + m)*HW + 2*(size_t)(pair0 + pp)) = o;
    }
}

// ---------------------------------------------------------------------------
// Pool (R4 shape verbatim — the ~8.5us pool): pure stream, no smem.
// grid (PNCH, CG*PFS, BS) = 4096 blocks, 256 thr = 8 warps, warp owns one
// channel, 8 frames per block, lane owns pixel pair (LDG.64).
// ---------------------------------------------------------------------------
__global__ void __launch_bounds__(256)
pool_kernel(const float* __restrict__ dec, const float* __restrict__ masks)
{
    const int tid  = threadIdx.x;
    const int wid  = tid >> 5;
    const int lane = tid & 31;

    const int ch = blockIdx.x;
    const int cg = blockIdx.y & (CG-1);
    const int fs = blockIdx.y >> 2;
    const int b  = blockIdx.z;
    const int c  = cg*8 + wid;

    // mask pixel-pairs for this chunk (L1/L2-hot: shared by all 8 warps)
    ull mk[NM];
#pragma unroll
    for (int m = 0; m < NM; m++)
        mk[m] = *reinterpret_cast<const ull*>(
            masks + ((size_t)b*NM + m)*HW + (size_t)ch*PCHUNK + 2*lane);

    ull acc[NM];
#pragma unroll
    for (int m = 0; m < NM; m++) acc[m] = 0ULL;

    const float* base = dec + (((size_t)(b*NF + fs*PFG))*C + c)*HW
                            + (size_t)ch*PCHUNK;

#pragma unroll
    for (int f = 0; f < PFG; f++) {
        ull v = reinterpret_cast<const ull*>(base + (size_t)f*C*HW)[lane];
#pragma unroll
        for (int m = 0; m < NM; m++)
            asm("fma.rn.f32x2 %0, %1, %2, %0;" : "+l"(acc[m]) : "l"(v), "l"(mk[m]));
    }

#pragma unroll
    for (int m = 0; m < NM; m++) {
        float2 a = *reinterpret_cast<float2*>(&acc[m]);
        float s = a.x + a.y;
#pragma unroll
        for (int off = 16; off; off >>= 1)
            s += __shfl_xor_sync(0xffffffffu, s, off);
        if (lane == 0)
            g_part[((((size_t)b*C + c)*NM + m)*PFS + fs)*PNCH + ch] = s;
    }
}

// ---------------------------------------------------------------------------
// Reduce + logits (K6-proven pattern): 512 blocks x 128 thr; block reduces
// one (b,c,m) row of 512 floats; LAST block computes the 48 logits.
// threadfence lives only in this cheap kernel.
// ---------------------------------------------------------------------------
__global__ void __launch_bounds__(128)
reduce_logits_kernel(const float* __restrict__ lw,
                     const float* __restrict__ lb,
                     float* __restrict__ out)
{
    const int row = blockIdx.x;            // (b*C + c)*NM + m
    const int tid = threadIdx.x;
    const float* src = g_part + (size_t)row * (PFS*PNCH);

    float s = src[tid] + src[tid+128] + src[tid+256] + src[tid+384];
#pragma unroll
    for (int off = 16; off; off >>= 1)
        s += __shfl_xor_sync(0xffffffffu, s, off);

    __shared__ float ws[4];
    __shared__ bool  is_last;
    if ((tid & 31) == 0) ws[tid >> 5] = s;
    __syncthreads();

    if (tid == 0) {
        float t = (ws[0] + ws[1] + ws[2] + ws[3]) * (1.0f / NF);
        int m = row & (NM-1);
        int c = (row / NM) & (C-1);
        int b = row / (NM*C);
        g_pooled[((size_t)b*NM + m)*C + c] = t;
        __threadfence();
        is_last = (atomicAdd(&g_ctr, 1) == gridDim.x - 1);
    }
    __syncthreads();

    if (is_last) {
        __threadfence();                   // acquire pooled writes
        if (tid < BS*NM*NK) {
            int k  = tid % NK;
            int bm = tid / NK;
            const float* p = g_pooled + (size_t)bm*C;
            float acc = lb[k];
#pragma unroll
            for (int c = 0; c < C; c++) acc += p[c] * lw[k*C + c];
            out[tid] = acc;
        }
        if (tid == 0) g_ctr = 0;           // reset for next graph replay
    }
}

// ---------------------------------------------------------------------------
extern "C" void kernel_launch(void* const* d_in, const int* in_sizes, int n_in,
                              void* d_out, int out_size)
{
    const float* dec   = (const float*)d_in[0];
    const float* seg_w = (const float*)d_in[1];
    const float* seg_b = (const float*)d_in[2];
    const float* lw    = (const float*)d_in[3];
    const float* lb    = (const float*)d_in[4];

    float* out    = (float*)d_out;
    float* logits = out;                 // 48 floats
    float* masks  = out + BS*NM*NK;      // 262144 floats

    masks_kernel        <<<dim3(HW/2/MPAIR, BS), 256>>>(dec, seg_w, seg_b, masks);
    pool_kernel         <<<dim3(PNCH, CG*PFS, BS), 256>>>(dec, masks);
    reduce_logits_kernel<<<BS*C*NM, 128>>>(lw, lb, logits);
}

// round 16
// speedup vs baseline: 1.4483x; 1.1828x over previous
#include <cuda_runtime.h>
#include <cstdint>

#define BS 2
#define NF 16
#define C  32
#define H  128
#define W  128
#define HW (H*W)
#define NM 8
#define NK 3
#define MID (NF/2)

#define PCHUNK 128           // pixels per pool block
#define PNCH (HW/PCHUNK)     // 128 chunks
#define CGRP 8               // channel groups of 4 (two warps per channel)

#define MPAIR 32             // pixel pairs per masks block

typedef unsigned long long ull;

// partials: row r=((b*C+c)*NM+m), PNCH=128 floats per row (256 KB)
__device__ float g_part[BS*C*NM*PNCH];
__device__ float g_pooled[BS*NM*C];
__device__ int   g_ctr;          // zero-init; self-resets each launch

__device__ __forceinline__ ull pack2(float a, float b) {
    ull r; asm("mov.b64 %0,{%1,%2};" : "=l"(r) : "f"(a), "f"(b)); return r;
}

// ---------------------------------------------------------------------------
// Masks v2: grid (HW/2/MPAIR, BS) = (256, 2) = 512 blocks, 256 threads.
// thread = (pair 0..31, qg 0..7); 4 float2 loads (channels qg*4..qg*4+3),
// partials combined through smem, bias added, float2 stores.
// ---------------------------------------------------------------------------
__global__ void __launch_bounds__(256)
masks_kernel(const float* __restrict__ dec,
             const float* __restrict__ seg_w,
             const float* __restrict__ seg_b,
             float* __restrict__ masks_out)
{
    __shared__ float2 part[8][NM][MPAIR];   // 16 KB
    __shared__ float  sw[NM*C];             // 1 KB

    const int tid = threadIdx.x;
    if (tid < NM*C) sw[tid] = seg_w[tid];
    __syncthreads();

    const int b     = blockIdx.y;
    const int pair0 = blockIdx.x * MPAIR;
    const int pr    = tid & (MPAIR-1);      // 0..31
    const int qg    = tid >> 5;             // 0..7 -> channels qg*4..qg*4+3

    const float* src = dec + ((size_t)(b*NF + MID)*C + qg*4)*HW
                           + 2*(size_t)(pair0 + pr);
    float2 v[4];
#pragma unroll
    for (int i = 0; i < 4; i++)
        v[i] = *reinterpret_cast<const float2*>(src + (size_t)i*HW);

    float2 pm[NM];
#pragma unroll
    for (int m = 0; m < NM; m++) pm[m] = make_float2(0.f, 0.f);
#pragma unroll
    for (int i = 0; i < 4; i++)
#pragma unroll
        for (int m = 0; m < NM; m++) {
            float w = sw[m*C + qg*4 + i];
            pm[m].x += v[i].x * w;
            pm[m].y += v[i].y * w;
        }
#pragma unroll
    for (int m = 0; m < NM; m++) part[qg][m][pr] = pm[m];
    __syncthreads();

    // combine: 8 masks x 32 pairs = 256 float2 / 256 thr = 1 each
    {
        int m  = tid >> 5;
        int pp = tid & (MPAIR-1);
        float2 o = make_float2(seg_b[m], seg_b[m]);
#pragma unroll
        for (int q = 0; q < 8; q++) {
            float2 a = part[q][m][pp];
            o.x += a.x; o.y += a.y;
        }
        *reinterpret_cast<float2*>(
            masks_out + ((size_t)b*NM + m)*HW + 2*(size_t)(pair0 + pp)) = o;
    }
}

// ---------------------------------------------------------------------------
// Pool v2 (mask-split warps): grid (PNCH, CGRP, BS) = 2048 blocks, 256 thr.
// Warp w: channel c = cg*4 + (w>>1), mask half mh = (w&1)*4.
// Per-warp state: 4 masks (mkA/mkB 16 regs) + acc 8 regs -> ~50 regs total,
// so 4+ CTAs/SM and 2x the in-flight LDG.128s of the K6 pool.
// ---------------------------------------------------------------------------
__global__ void __launch_bounds__(256)
pool_kernel(const float* __restrict__ dec, const float* __restrict__ masks)
{
    const int tid  = threadIdx.x;
    const int wid  = tid >> 5;
    const int lane = tid & 31;

    const int ch = blockIdx.x;
    const int cg = blockIdx.y;
    const int b  = blockIdx.z;
    const int c  = cg*4 + (wid >> 1);
    const int mh = (wid & 1) * 4;          // mask base: 0 or 4

    ull mkA[4], mkB[4];
#pragma unroll
    for (int m = 0; m < 4; m++) {
        float4 mv = reinterpret_cast<const float4*>(
            masks + ((size_t)b*NM + mh + m)*HW + (size_t)ch*PCHUNK)[lane];
        mkA[m] = pack2(mv.x, mv.y);
        mkB[m] = pack2(mv.z, mv.w);
    }

    ull acc[4];
#pragma unroll
    for (int m = 0; m < 4; m++) acc[m] = 0ULL;

    const float* base = dec + ((size_t)b*NF*C + c)*HW + (size_t)ch*PCHUNK;

    // single-frame double buffer: 2 LDG.128 outstanding per warp
    float4 cur = reinterpret_cast<const float4*>(base)[lane];
#pragma unroll
    for (int f = 0; f < NF; f++) {
        float4 nxt = cur;
        if (f < NF-1)
            nxt = reinterpret_cast<const float4*>(base + (size_t)(f+1)*C*HW)[lane];
        ull v01 = pack2(cur.x, cur.y);
        ull v23 = pack2(cur.z, cur.w);
#pragma unroll
        for (int m = 0; m < 4; m++) {
            asm("fma.rn.f32x2 %0, %1, %2, %0;" : "+l"(acc[m]) : "l"(v01), "l"(mkA[m]));
            asm("fma.rn.f32x2 %0, %1, %2, %0;" : "+l"(acc[m]) : "l"(v23), "l"(mkB[m]));
        }
        cur = nxt;
    }

#pragma unroll
    for (int m = 0; m < 4; m++) {
        float2 a = *reinterpret_cast<float2*>(&acc[m]);
        float s = a.x + a.y;
#pragma unroll
        for (int off = 16; off; off >>= 1)
            s += __shfl_xor_sync(0xffffffffu, s, off);
        if (lane == 0)
            g_part[(((size_t)b*C + c)*NM + mh + m)*PNCH + ch] = s;
    }
}

// ---------------------------------------------------------------------------
// Reduce + logits (K6 verbatim): 512 blocks x 128 thr; block reduces one
// (b,c,m) row of 128 floats; LAST block computes the 48 logits.
// ---------------------------------------------------------------------------
__global__ void __launch_bounds__(128)
reduce_logits_kernel(const float* __restrict__ lw,
                     const float* __restrict__ lb,
                     float* __restrict__ out)
{
    const int row = blockIdx.x;            // (b*C + c)*NM + m
    const int tid = threadIdx.x;

    float s = g_part[(size_t)row*PNCH + tid];
#pragma unroll
    for (int off = 16; off; off >>= 1)
        s += __shfl_xor_sync(0xffffffffu, s, off);

    __shared__ float ws[4];
    __shared__ bool  is_last;
    if ((tid & 31) == 0) ws[tid >> 5] = s;
    __syncthreads();

    if (tid == 0) {
        float t = (ws[0] + ws[1] + ws[2] + ws[3]) * (1.0f / NF);
        int m = row & (NM-1);
        int c = (row / NM) & (C-1);
        int b = row / (NM*C);
        g_pooled[((size_t)b*NM + m)*C + c] = t;
        __threadfence();
        is_last = (atomicAdd(&g_ctr, 1) == gridDim.x - 1);
    }
    __syncthreads();

    if (is_last) {
        __threadfence();                   // acquire pooled writes
        if (tid < BS*NM*NK) {
            int k  = tid % NK;
            int bm = tid / NK;
            const float* p = g_pooled + (size_t)bm*C;
            float acc = lb[k];
#pragma unroll
            for (int c = 0; c < C; c++) acc += p[c] * lw[k*C + c];
            out[tid] = acc;
        }
        if (tid == 0) g_ctr = 0;           // reset for next graph replay
    }
}

// ---------------------------------------------------------------------------
extern "C" void kernel_launch(void* const* d_in, const int* in_sizes, int n_in,
                              void* d_out, int out_size)
{
    const float* dec   = (const float*)d_in[0];
    const float* seg_w = (const float*)d_in[1];
    const float* seg_b = (const float*)d_in[2];
    const float* lw    = (const float*)d_in[3];
    const float* lb    = (const float*)d_in[4];

    float* out    = (float*)d_out;
    float* logits = out;                 // 48 floats
    float* masks  = out + BS*NM*NK;      // 262144 floats

    masks_kernel        <<<dim3(HW/2/MPAIR, BS), 256>>>(dec, seg_w, seg_b, masks);
    pool_kernel         <<<dim3(PNCH, CGRP, BS), 256>>>(dec, masks);
    reduce_logits_kernel<<<BS*C*NM, 128>>>(lw, lb, logits);
}

// round 17
// speedup vs baseline: 1.5415x; 1.0643x over previous
#include <cuda_runtime.h>
#include <cstdint>

#define BS 2
#define NF 16
#define C  32
#define H  128
#define W  128
#define HW (H*W)
#define NM 8
#define NK 3
#define MID (NF/2)

#define PCHUNK 128           // pixels per pool block
#define PNCH (HW/PCHUNK)     // 128 chunks
#define CG 4                 // channel groups of 8 (one warp per channel)

#define MPAIR 64             // pixel pairs per masks block

#define STAGES 8             // cp.async pipeline depth (frames)
#define SSTRIDE (8*32*16)    // bytes per stage: 8 warps x 32 lanes x 16B = 4 KB

typedef unsigned long long ull;

// partials: row r=((b*C+c)*NM+m), PNCH=128 floats per row (256 KB)
__device__ float g_part[BS*C*NM*PNCH];
__device__ float g_pooled[BS*NM*C];
__device__ int   g_ctr;          // zero-init; self-resets each launch

__device__ __forceinline__ ull pack2(float a, float b) {
    ull r; asm("mov.b64 %0,{%1,%2};" : "=l"(r) : "f"(a), "f"(b)); return r;
}

// ---------------------------------------------------------------------------
// Masks (R10/K13 shape): grid (HW/2/MPAIR, BS) = 256 blocks, 256 threads.
// ---------------------------------------------------------------------------
__global__ void __launch_bounds__(256)
masks_kernel(const float* __restrict__ dec,
             const float* __restrict__ seg_w,
             const float* __restrict__ seg_b,
             float* __restrict__ masks_out)
{
    __shared__ float2 part[4][NM][MPAIR];   // 16 KB
    __shared__ float  sw[NM*C];             // 1 KB

    const int tid = threadIdx.x;
    if (tid < NM*C) sw[tid] = seg_w[tid];
    __syncthreads();

    const int b     = blockIdx.y;
    const int pair0 = blockIdx.x * MPAIR;
    const int pr    = tid & (MPAIR-1);
    const int qc    = tid >> 6;             // 0..3

    const float* src = dec + ((size_t)(b*NF + MID)*C + qc*8)*HW
                           + 2*(size_t)(pair0 + pr);
    float2 v[8];
#pragma unroll
    for (int i = 0; i < 8; i++)
        v[i] = *reinterpret_cast<const float2*>(src + (size_t)i*HW);

    float2 pm[NM];
#pragma unroll
    for (int m = 0; m < NM; m++) pm[m] = make_float2(0.f, 0.f);
#pragma unroll
    for (int i = 0; i < 8; i++)
#pragma unroll
        for (int m = 0; m < NM; m++) {
            float w = sw[m*C + qc*8 + i];
            pm[m].x += v[i].x * w;
            pm[m].y += v[i].y * w;
        }
#pragma unroll
    for (int m = 0; m < NM; m++) part[qc][m][pr] = pm[m];
    __syncthreads();

#pragma unroll
    for (int r = 0; r < 2; r++) {
        int k  = tid + r*256;
        int m  = k >> 6;
        int pp = k & (MPAIR-1);
        float2 a0 = part[0][m][pp], a1 = part[1][m][pp];
        float2 a2 = part[2][m][pp], a3 = part[3][m][pp];
        float bsc = seg_b[m];
        float2 o = make_float2(a0.x+a1.x+a2.x+a3.x + bsc,
                               a0.y+a1.y+a2.y+a3.y + bsc);
        *reinterpret_cast<float2*>(
            masks_out + ((size_t)b*NM + m)*HW + 2*(size_t)(pair0 + pp)) = o;
    }
}

// ---------------------------------------------------------------------------
// Pool with cp.async staging: grid (PNCH, CG, BS) = 1024 blocks, 256 thr.
// Warp owns one channel; lane owns 4 px. Frames stream through an 8-stage
// smem ring via cp.async (16 B per lane per frame) -> 7 groups in flight,
// in-flight bytes decoupled from register allocation. Each lane reads back
// exactly the float4 it loaded -> no block/warp syncs in the mainloop.
// ---------------------------------------------------------------------------
__global__ void __launch_bounds__(256)
pool_kernel(const float* __restrict__ dec, const float* __restrict__ masks)
{
    __shared__ float4 sbuf[STAGES][8][32];  // 32 KB ring

    const int tid  = threadIdx.x;
    const int wid  = tid >> 5;
    const int lane = tid & 31;

    const int ch = blockIdx.x;
    const int cg = blockIdx.y;
    const int b  = blockIdx.z;
    const int c  = cg*8 + wid;

    // masks (L2-hot: written by masks_kernel just before)
    ull mkA[NM], mkB[NM];
#pragma unroll
    for (int m = 0; m < NM; m++) {
        float4 mv = reinterpret_cast<const float4*>(
            masks + ((size_t)b*NM + m)*HW + (size_t)ch*PCHUNK)[lane];
        mkA[m] = pack2(mv.x, mv.y);
        mkB[m] = pack2(mv.z, mv.w);
    }

    ull acc[NM];
#pragma unroll
    for (int m = 0; m < NM; m++) acc[m] = 0ULL;

    const float* base = dec + ((size_t)b*NF*C + c)*HW
                            + (size_t)ch*PCHUNK + lane*4;
    const uint32_t saddr =
        (uint32_t)__cvta_generic_to_shared(&sbuf[0][wid][lane]);

    // prologue: frames 0..6, one commit group each
#pragma unroll
    for (int k = 0; k < STAGES-1; k++) {
        uint32_t dst = saddr + (k & (STAGES-1))*SSTRIDE;
        const float* g = base + (size_t)k*C*HW;
        asm volatile("cp.async.cg.shared.global [%0], [%1], 16;\n"
                     :: "r"(dst), "l"(g) : "memory");
        asm volatile("cp.async.commit_group;\n" ::: "memory");
    }

#pragma unroll
    for (int f = 0; f < NF; f++) {
        asm volatile("cp.async.wait_group %0;\n" :: "n"(STAGES-2) : "memory");
        float4 v = sbuf[f & (STAGES-1)][wid][lane];

        ull v01 = pack2(v.x, v.y);
        ull v23 = pack2(v.z, v.w);
#pragma unroll
        for (int m = 0; m < NM; m++) {
            asm("fma.rn.f32x2 %0, %1, %2, %0;" : "+l"(acc[m]) : "l"(v01), "l"(mkA[m]));
            asm("fma.rn.f32x2 %0, %1, %2, %0;" : "+l"(acc[m]) : "l"(v23), "l"(mkB[m]));
        }

        int nf = f + STAGES-1;
        if (nf < NF) {
            uint32_t dst = saddr + (nf & (STAGES-1))*SSTRIDE;
            const float* g = base + (size_t)nf*C*HW;
            asm volatile("cp.async.cg.shared.global [%0], [%1], 16;\n"
                         :: "r"(dst), "l"(g) : "memory");
        }
        asm volatile("cp.async.commit_group;\n" ::: "memory");
    }

#pragma unroll
    for (int m = 0; m < NM; m++) {
        float2 a = *reinterpret_cast<float2*>(&acc[m]);
        float s = a.x + a.y;
#pragma unroll
        for (int off = 16; off; off >>= 1)
            s += __shfl_xor_sync(0xffffffffu, s, off);
        if (lane == 0)
            g_part[(((size_t)b*C + c)*NM + m)*PNCH + ch] = s;
    }
}

// ---------------------------------------------------------------------------
// Reduce + logits (K6 verbatim): 512 blocks x 128 thr.
// ---------------------------------------------------------------------------
__global__ void __launch_bounds__(128)
reduce_logits_kernel(const float* __restrict__ lw,
                     const float* __restrict__ lb,
                     float* __restrict__ out)
{
    const int row = blockIdx.x;            // (b*C + c)*NM + m
    const int tid = threadIdx.x;

    float s = g_part[(size_t)row*PNCH + tid];
#pragma unroll
    for (int off = 16; off; off >>= 1)
        s += __shfl_xor_sync(0xffffffffu, s, off);

    __shared__ float ws[4];
    __shared__ bool  is_last;
    if ((tid & 31) == 0) ws[tid >> 5] = s;
    __syncthreads();

    if (tid == 0) {
        float t = (ws[0] + ws[1] + ws[2] + ws[3]) * (1.0f / NF);
        int m = row & (NM-1);
        int c = (row / NM) & (C-1);
        int b = row / (NM*C);
        g_pooled[((size_t)b*NM + m)*C + c] = t;
        __threadfence();
        is_last = (atomicAdd(&g_ctr, 1) == gridDim.x - 1);
    }
    __syncthreads();

    if (is_last) {
        __threadfence();                   // acquire pooled writes
        if (tid < BS*NM*NK) {
            int k  = tid % NK;
            int bm = tid / NK;
            const float* p = g_pooled + (size_t)bm*C;
            float acc = lb[k];
#pragma unroll
            for (int c = 0; c < C; c++) acc += p[c] * lw[k*C + c];
            out[tid] = acc;
        }
        if (tid == 0) g_ctr = 0;           // reset for next graph replay
    }
}

// ---------------------------------------------------------------------------
extern "C" void kernel_launch(void* const* d_in, const int* in_sizes, int n_in,
                              void* d_out, int out_size)
{
    const float* dec   = (const float*)d_in[0];
    const float* seg_w = (const float*)d_in[1];
    const float* seg_b = (const float*)d_in[2];
    const float* lw    = (const float*)d_in[3];
    const float* lb    = (const float*)d_in[4];

    float* out    = (float*)d_out;
    float* logits = out;                 // 48 floats
    float* masks  = out + BS*NM*NK;      // 262144 floats

    masks_kernel        <<<dim3(HW/2/MPAIR, BS), 256>>>(dec, seg_w, seg_b, masks);
    pool_kernel         <<<dim3(PNCH, CG, BS), 256>>>(dec, masks);
    reduce_logits_kernel<<<BS*C*NM, 128>>>(lw, lb, logits);
}